// round 13
// baseline (speedup 1.0000x reference)
#include <cuda_runtime.h>
#include <cuda.h>
#include <cuda_fp16.h>
#include <math.h>
#include <stdint.h>
#include <string.h>

// Problem dims
#define Bq 8
#define Tq 2048
#define Dq 1024
#define Fq 4096
#define Eq 8
#define NPAIR 16

// GEMM tiling: CTA 128x128x64, 8 compute warps (32x64) + 1 TMA producer, occ 2
#define NST 3
#define A_BYTES 16384
#define B_BYTES 16384
#define STAGE_BYTES (A_BYTES + B_BYTES)   // 32768
#define SMEM_REQ (2048 + NST*STAGE_BYTES)
#define NTHR 288

// tile counts
#define NT1 (32*16*NPAIR)    // 8192: nx(32) fastest, my(16), pair(16)
#define NT2 (8*16*Bq)        // 1024: nx(8) fastest, my(16), b(8)

// prep kernel block ranges
#define XBLK 256
#define WBLK 8192

// ---------------- device scratch ----------------
__device__ __half g_xh [(size_t)Bq*Tq*Dq];        // x fp16        [B][T][D]
__device__ __half g_w1h[(size_t)Eq*Dq*Fq];        // W1 fp16       [E][D][F]
__device__ __half g_w2h[(size_t)Eq*Fq*Dq];        // W2 fp16       [E][F][D]
__device__ __half g_h  [(size_t)NPAIR*Tq*Fq];     // w*gelu(..)    [P][T][F]
__device__ float  g_part[Bq*8*Dq];
__device__ int    g_re[NPAIR];
__device__ float  g_rw[NPAIR];

// ---------------- helpers ----------------
__device__ __forceinline__ uint32_t cvt_smem(const void* p) {
    return (uint32_t)__cvta_generic_to_shared(p);
}
__device__ __forceinline__ void mbar_init(uint32_t a, uint32_t cnt) {
    asm volatile("mbarrier.init.shared.b64 [%0], %1;" :: "r"(a), "r"(cnt) : "memory");
}
__device__ __forceinline__ void mbar_expect(uint32_t a, uint32_t bytes) {
    asm volatile("mbarrier.arrive.expect_tx.shared.b64 _, [%0], %1;"
        :: "r"(a), "r"(bytes) : "memory");
}
__device__ __forceinline__ void mbar_arrive(uint32_t a) {
    asm volatile("mbarrier.arrive.shared.b64 _, [%0];" :: "r"(a) : "memory");
}
__device__ __forceinline__ void mbar_wait(uint32_t a, uint32_t parity) {
    asm volatile("{\n\t.reg .pred P;\n"
        "W%=:\n\t"
        "mbarrier.try_wait.parity.acquire.cta.shared::cta.b64 P, [%0], %1;\n\t"
        "@!P bra W%=;\n\t}"
        :: "r"(a), "r"(parity) : "memory");
}
__device__ __forceinline__ void mbar_wait_relaxed(uint32_t a, uint32_t parity) {
    asm volatile("{\n\t.reg .pred P;\n"
        "W%=:\n\t"
        "mbarrier.try_wait.parity.relaxed.cta.shared::cta.b64 P, [%0], %1;\n\t"
        "@!P bra W%=;\n\t}"
        :: "r"(a), "r"(parity) : "memory");
}
__device__ __forceinline__ void tma3(uint32_t dst, const CUtensorMap* m,
                                     int x, int y, int z, uint32_t mbar) {
    asm volatile(
        "cp.async.bulk.tensor.3d.shared::cta.global.tile.mbarrier::complete_tx::bytes "
        "[%0], [%1, {%2, %3, %4}], [%5];"
        :: "r"(dst), "l"(m), "r"(x), "r"(y), "r"(z), "r"(mbar) : "memory");
}
__device__ __forceinline__ uint32_t pkh2(float a, float b) {
    __half2 h = __floats2half2_rn(a, b);
    uint32_t r; memcpy(&r, &h, 4); return r;
}

// ---------------- merged prep: x conv+pool partials, W1 f2h, W2 f2h ----------------
__device__ __forceinline__ void f2h_body(const float4* __restrict__ s,
                                         uint4* __restrict__ d, size_t i) {
    const float4* sp = s + 4*i;
    float4 v0 = sp[0], v1 = sp[1], v2 = sp[2], v3 = sp[3];
    uint4 o0, o1;
    o0.x = pkh2(v0.x, v0.y); o0.y = pkh2(v0.z, v0.w);
    o0.z = pkh2(v1.x, v1.y); o0.w = pkh2(v1.z, v1.w);
    o1.x = pkh2(v2.x, v2.y); o1.y = pkh2(v2.z, v2.w);
    o1.z = pkh2(v3.x, v3.y); o1.w = pkh2(v3.z, v3.w);
    uint4* dp = d + 2*i;
    dp[0] = o0; dp[1] = o1;
}

__global__ void prep_kernel(const float* __restrict__ x,
                            const float* __restrict__ W1,
                            const float* __restrict__ W2,
                            __half* __restrict__ xh,
                            __half* __restrict__ w1h,
                            __half* __restrict__ w2h) {
    int j = blockIdx.x;
    if (j < XBLK) {
        int d  = (j & 3) * 256 + threadIdx.x;
        int tc = (j >> 2) & 7;
        int b  = j >> 5;
        const float* p = x  + ((size_t)b * Tq + (size_t)tc * 256) * Dq + d;
        __half*      q = xh + ((size_t)b * Tq + (size_t)tc * 256) * Dq + d;
        float s = 0.f;
        #pragma unroll 8
        for (int t = 0; t < 256; t++) {
            float v = p[(size_t)t * Dq];
            s += v;
            q[(size_t)t * Dq] = __float2half_rn(v);
        }
        g_part[(b*8 + tc)*Dq + d] = s;
    } else if (j < XBLK + WBLK) {
        size_t i = (size_t)(j - XBLK) * 256 + threadIdx.x;
        f2h_body((const float4*)W1, (uint4*)w1h, i);
    } else {
        size_t i = (size_t)(j - XBLK - WBLK) * 256 + threadIdx.x;
        f2h_body((const float4*)W2, (uint4*)w2h, i);
    }
}

// ---------------- router: 8 blocks, one per sample ----------------
__global__ void router8_kernel(const float* __restrict__ Wr) {
    __shared__ float pooled[Dq];
    __shared__ float logit[Eq];
    int b = blockIdx.x, tid = threadIdx.x;
    for (int d = tid; d < Dq; d += 256) {
        float s = 0.f;
        #pragma unroll
        for (int c = 0; c < 8; c++) s += g_part[(b*8 + c)*Dq + d];
        pooled[d] = s * (1.0f / (float)Tq);
    }
    __syncthreads();
    int warp = tid >> 5, lane = tid & 31;
    float s = 0.f;
    for (int d = lane; d < Dq; d += 32)
        s += pooled[d] * Wr[d*Eq + warp];
    #pragma unroll
    for (int o = 16; o > 0; o >>= 1) s += __shfl_xor_sync(0xffffffffu, s, o);
    if (lane == 0) logit[warp] = s;
    __syncthreads();
    if (tid == 0) {
        float best = -1e30f; int bi = 0;
        for (int e = 0; e < Eq; e++) { float v = logit[e]; if (v > best) { best = v; bi = e; } }
        float best2 = -1e30f; int bi2 = 0;
        for (int e = 0; e < Eq; e++) { if (e == bi) continue; float v = logit[e]; if (v > best2) { best2 = v; bi2 = e; } }
        float e1 = expf(best2 - best);
        float inv = 1.0f / (1.0f + e1);
        g_re[b*2+0] = bi;  g_rw[b*2+0] = inv;
        g_re[b*2+1] = bi2; g_rw[b*2+1] = e1 * inv;
    }
}

// ---------------- compute: warp tile 32x64, ldmatrix + mma ----------------
__device__ __forceinline__ void compute_iter(uint32_t sA, uint32_t sB,
        float acc[2][8][4], int wm, int wn, int lane) {
    #pragma unroll
    for (int ki = 0; ki < 4; ki++) {
        uint32_t a[2][4];
        #pragma unroll
        for (int mi = 0; mi < 2; mi++) {
            int r = wm*32 + mi*16 + (lane & 15);
            int c = ki*2 + (lane >> 4);
            uint32_t addr = sA + r*128 + ((c ^ (r & 7)) << 4);
            asm volatile("ldmatrix.sync.aligned.m8n8.x4.shared.b16 {%0,%1,%2,%3}, [%4];\n"
                : "=r"(a[mi][0]), "=r"(a[mi][1]), "=r"(a[mi][2]), "=r"(a[mi][3]) : "r"(addr));
        }
        uint32_t bf[8][2];
        #pragma unroll
        for (int n2 = 0; n2 < 4; n2++) {
            int kk = ki*16 + (lane & 15);
            int cl = n2*2 + (lane >> 4);
            uint32_t addr = sB + wn*8192 + kk*128 + (((cl ^ kk) & 7) << 4);
            asm volatile("ldmatrix.sync.aligned.m8n8.x4.trans.shared.b16 {%0,%1,%2,%3}, [%4];\n"
                : "=r"(bf[2*n2][0]), "=r"(bf[2*n2][1]), "=r"(bf[2*n2+1][0]), "=r"(bf[2*n2+1][1])
                : "r"(addr));
        }
        #pragma unroll
        for (int mi = 0; mi < 2; mi++)
            #pragma unroll
            for (int ni = 0; ni < 8; ni++) {
                asm volatile(
                    "mma.sync.aligned.m16n8k16.row.col.f32.f16.f16.f32 "
                    "{%0,%1,%2,%3}, {%4,%5,%6,%7}, {%8,%9}, {%0,%1,%2,%3};\n"
                    : "+f"(acc[mi][ni][0]), "+f"(acc[mi][ni][1]),
                      "+f"(acc[mi][ni][2]), "+f"(acc[mi][ni][3])
                    : "r"(a[mi][0]), "r"(a[mi][1]), "r"(a[mi][2]), "r"(a[mi][3]),
                      "r"(bf[ni][0]), "r"(bf[ni][1]));
            }
    }
}

// Rolling pipeline state shared by producer/consumer code paths.
struct PipeCur { int s; int ph; };
__device__ __forceinline__ void pipe_adv(PipeCur& c) {
    if (++c.s == NST) { c.s = 0; c.ph ^= 1; }
}

// ---------------- GEMM1 (persistent): H[pair] = w * gelu(x[b] @ W1[e] + b1[e]) ----------------
__global__ void __launch_bounds__(NTHR, 2) gemm1_k(
        const __grid_constant__ CUtensorMap mA, const __grid_constant__ CUtensorMap mB,
        const float* __restrict__ b1) {
    extern __shared__ __align__(16) char smraw[];
    uint32_t u = cvt_smem(smraw);
    uint32_t base = (u + 1023) & ~1023u;
    uint32_t full = base, empty = base + 24;
    uint32_t st = base + 1024;
    int tid = threadIdx.x, lane = tid & 31, wid = tid >> 5;
    int wm = wid & 3, wn = wid >> 2;

    if (tid == 0) {
        #pragma unroll
        for (int s = 0; s < NST; s++) { mbar_init(full + s*8, 1); mbar_init(empty + s*8, 8); }
    }
    __syncthreads();

    if (wid == 8) {
        if (lane == 0) {
            PipeCur c = {0, 0};
            int it = 0;
            for (int t = blockIdx.x; t < NT1; t += gridDim.x) {
                int nx = t & 31, my = (t >> 5) & 15, pair = t >> 9;
                int e = g_re[pair], b = pair >> 1;
                int am0 = my*128, bn0 = nx*128;
                #pragma unroll 1
                for (int kt = 0; kt < 16; kt++, it++) {
                    if (it >= NST) mbar_wait_relaxed(empty + c.s*8, c.ph ^ 1);
                    uint32_t so = st + (uint32_t)c.s * STAGE_BYTES;
                    uint32_t mb = full + c.s*8;
                    mbar_expect(mb, STAGE_BYTES);
                    tma3(so,                &mA, kt*64,    am0,   b, mb);
                    tma3(so + A_BYTES,      &mB, bn0,      kt*64, e, mb);
                    tma3(so + A_BYTES+8192, &mB, bn0 + 64, kt*64, e, mb);
                    pipe_adv(c);
                }
            }
        }
    } else {
        PipeCur c = {0, 0};
        int tg = lane >> 2, tl = lane & 3;
        for (int t = blockIdx.x; t < NT1; t += gridDim.x) {
            int nx = t & 31, my = (t >> 5) & 15, pair = t >> 9;
            int e = g_re[pair];
            float w = g_rw[pair];
            float acc[2][8][4];
            #pragma unroll
            for (int i = 0; i < 2; i++) for (int j = 0; j < 8; j++)
                for (int q = 0; q < 4; q++) acc[i][j][q] = 0.f;
            #pragma unroll 1
            for (int kt = 0; kt < 16; kt++) {
                mbar_wait(full + c.s*8, c.ph);
                compute_iter(st + (uint32_t)c.s*STAGE_BYTES,
                             st + (uint32_t)c.s*STAGE_BYTES + A_BYTES, acc, wm, wn, lane);
                if (lane == 0) mbar_arrive(empty + c.s*8);
                pipe_adv(c);
            }
            const float* b1e = b1 + e*Fq + nx*128;
            __half* H = g_h + ((size_t)pair * Tq + (size_t)my*128) * Fq + nx*128;
            #pragma unroll
            for (int mi = 0; mi < 2; mi++) {
                #pragma unroll
                for (int ni = 0; ni < 8; ni++) {
                    int col  = wn*64 + ni*8 + tl*2;
                    int row0 = wm*32 + mi*16 + tg;
                    float bias0 = b1e[col], bias1 = b1e[col+1];
                    #pragma unroll
                    for (int rr = 0; rr < 2; rr++) {
                        float v0 = acc[mi][ni][rr*2+0] + bias0;
                        float v1 = acc[mi][ni][rr*2+1] + bias1;
                        v0 = 0.5f * v0 * (1.0f + erff(v0 * 0.7071067811865476f));
                        v1 = 0.5f * v1 * (1.0f + erff(v1 * 0.7071067811865476f));
                        *(__half2*)(H + (size_t)(row0 + rr*8) * Fq + col) =
                            __floats2half2_rn(v0*w, v1*w);
                    }
                }
            }
        }
    }
}

// ---------------- GEMM2 (persistent): out[b] = sum_k H[b,k] @ W2[e_k] + bias ----------------
__global__ void __launch_bounds__(NTHR, 2) gemm2_k(
        const __grid_constant__ CUtensorMap mA, const __grid_constant__ CUtensorMap mB,
        const float* __restrict__ b2, float* __restrict__ out) {
    extern __shared__ __align__(16) char smraw[];
    uint32_t u = cvt_smem(smraw);
    uint32_t base = (u + 1023) & ~1023u;
    uint32_t full = base, empty = base + 24;
    uint32_t st = base + 1024;
    int tid = threadIdx.x, lane = tid & 31, wid = tid >> 5;
    int wm = wid & 3, wn = wid >> 2;

    if (tid == 0) {
        #pragma unroll
        for (int s = 0; s < NST; s++) { mbar_init(full + s*8, 1); mbar_init(empty + s*8, 8); }
    }
    __syncthreads();

    if (wid == 8) {
        if (lane == 0) {
            PipeCur c = {0, 0};
            int it = 0;
            for (int t = blockIdx.x; t < NT2; t += gridDim.x) {
                int nx = t & 7, my = (t >> 3) & 15, b = t >> 7;
                int am0 = my*128, bn0 = nx*128;
                #pragma unroll 1
                for (int kt = 0; kt < 128; kt++, it++) {
                    int seg = kt >> 6, kk = kt & 63;
                    int az = b*2 + seg;
                    int bz = g_re[b*2 + seg];
                    if (it >= NST) mbar_wait_relaxed(empty + c.s*8, c.ph ^ 1);
                    uint32_t so = st + (uint32_t)c.s * STAGE_BYTES;
                    uint32_t mb = full + c.s*8;
                    mbar_expect(mb, STAGE_BYTES);
                    tma3(so,                &mA, kk*64,    am0,   az, mb);
                    tma3(so + A_BYTES,      &mB, bn0,      kk*64, bz, mb);
                    tma3(so + A_BYTES+8192, &mB, bn0 + 64, kk*64, bz, mb);
                    pipe_adv(c);
                }
            }
        }
    } else {
        PipeCur c = {0, 0};
        int tg = lane >> 2, tl = lane & 3;
        for (int t = blockIdx.x; t < NT2; t += gridDim.x) {
            int nx = t & 7, my = (t >> 3) & 15, b = t >> 7;
            float acc[2][8][4];
            #pragma unroll
            for (int i = 0; i < 2; i++) for (int j = 0; j < 8; j++)
                for (int q = 0; q < 4; q++) acc[i][j][q] = 0.f;
            #pragma unroll 1
            for (int kt = 0; kt < 128; kt++) {
                mbar_wait(full + c.s*8, c.ph);
                compute_iter(st + (uint32_t)c.s*STAGE_BYTES,
                             st + (uint32_t)c.s*STAGE_BYTES + A_BYTES, acc, wm, wn, lane);
                if (lane == 0) mbar_arrive(empty + c.s*8);
                pipe_adv(c);
            }
            int e0 = g_re[b*2], e1 = g_re[b*2+1];
            float w0 = g_rw[b*2], w1 = g_rw[b*2+1];
            const float* b2a = b2 + e0*Dq + nx*128;
            const float* b2b = b2 + e1*Dq + nx*128;
            float* O = out + ((size_t)b * Tq + (size_t)my*128) * Dq + nx*128;
            #pragma unroll
            for (int mi = 0; mi < 2; mi++) {
                #pragma unroll
                for (int ni = 0; ni < 8; ni++) {
                    int col  = wn*64 + ni*8 + tl*2;
                    int row0 = wm*32 + mi*16 + tg;
                    float bias0 = w0*b2a[col]   + w1*b2b[col];
                    float bias1 = w0*b2a[col+1] + w1*b2b[col+1];
                    #pragma unroll
                    for (int rr = 0; rr < 2; rr++) {
                        float2 v;
                        v.x = acc[mi][ni][rr*2+0] + bias0;
                        v.y = acc[mi][ni][rr*2+1] + bias1;
                        *(float2*)(O + (size_t)(row0 + rr*8) * Dq + col) = v;
                    }
                }
            }
        }
    }
}

// ---------------- host ----------------
typedef CUresult (*PFN_encode)(CUtensorMap*, CUtensorMapDataType, cuuint32_t, void*,
    const cuuint64_t*, const cuuint64_t*, const cuuint32_t*, const cuuint32_t*,
    CUtensorMapInterleave, CUtensorMapSwizzle, CUtensorMapL2promotion,
    CUtensorMapFloatOOBfill);

static void make_map(PFN_encode enc, CUtensorMap* m, void* ptr,
                     uint64_t d0, uint64_t d1, uint64_t d2, uint32_t boxy) {
    cuuint64_t dims[3]    = {d0, d1, d2};
    cuuint64_t strides[2] = {d0 * 2, d0 * d1 * 2};
    cuuint32_t box[3]     = {64, boxy, 1};
    cuuint32_t estr[3]    = {1, 1, 1};
    enc(m, CU_TENSOR_MAP_DATA_TYPE_FLOAT16, 3, ptr, dims, strides, box, estr,
        CU_TENSOR_MAP_INTERLEAVE_NONE, CU_TENSOR_MAP_SWIZZLE_128B,
        CU_TENSOR_MAP_L2_PROMOTION_L2_128B, CU_TENSOR_MAP_FLOAT_OOB_FILL_NONE);
}

extern "C" void kernel_launch(void* const* d_in, const int* in_sizes, int n_in,
                              void* d_out, int out_size) {
    const float* x  = (const float*)d_in[0];
    const float* Wr = (const float*)d_in[1];
    const float* W1 = (const float*)d_in[2];
    const float* b1 = (const float*)d_in[3];
    const float* W2 = (const float*)d_in[4];
    const float* b2 = (const float*)d_in[5];
    float* out = (float*)d_out;

    cudaFuncSetAttribute(gemm1_k, cudaFuncAttributeMaxDynamicSharedMemorySize, SMEM_REQ);
    cudaFuncSetAttribute(gemm2_k, cudaFuncAttributeMaxDynamicSharedMemorySize, SMEM_REQ);

    int smc = 148;
    cudaDeviceGetAttribute(&smc, cudaDevAttrMultiProcessorCount, 0);
    int npers = 2 * smc;
    int g1 = npers < NT1 ? npers : NT1;
    int g2 = npers < NT2 ? npers : NT2;

    void *pxh, *pw1h, *pw2h, *ph;
    cudaGetSymbolAddress(&pxh,  g_xh);
    cudaGetSymbolAddress(&pw1h, g_w1h);
    cudaGetSymbolAddress(&pw2h, g_w2h);
    cudaGetSymbolAddress(&ph,   g_h);

    PFN_encode enc = nullptr;
#if CUDART_VERSION >= 12050
    cudaDriverEntryPointQueryResult qr;
    cudaGetDriverEntryPointByVersion("cuTensorMapEncodeTiled", (void**)&enc, 12000,
                                     cudaEnableDefault, &qr);
#else
    cudaDriverEntryPointQueryResult qr;
    cudaGetDriverEntryPoint("cuTensorMapEncodeTiled", (void**)&enc, cudaEnableDefault, &qr);
#endif

    CUtensorMap mX, mW1, mH, mW2;
    make_map(enc, &mX,  pxh,  Dq, Tq, Bq,    128);  // x   [B][T][D]
    make_map(enc, &mW1, pw1h, Fq, Dq, Eq,     64);  // W1  [E][D][F]
    make_map(enc, &mH,  ph,   Fq, Tq, NPAIR, 128);  // H   [P][T][F]
    make_map(enc, &mW2, pw2h, Dq, Fq, Eq,     64);  // W2  [E][F][D]

    // single stream (graph-safe, no stream/event allocations)
    prep_kernel<<<XBLK + 2*WBLK, 256>>>(x, W1, W2,
        (__half*)pxh, (__half*)pw1h, (__half*)pw2h);                               // 0
    router8_kernel<<<Bq, 256>>>(Wr);                                               // 1
    gemm1_k<<<g1, NTHR, SMEM_REQ>>>(mX, mW1, b1);                                  // 2
    gemm2_k<<<g2, NTHR, SMEM_REQ>>>(mH, mW2, b2, out);                             // 3
}

// round 14
// speedup vs baseline: 1.0243x; 1.0243x over previous
#include <cuda_runtime.h>
#include <cuda.h>
#include <cuda_fp16.h>
#include <math.h>
#include <stdint.h>
#include <string.h>

// Problem dims
#define Bq 8
#define Tq 2048
#define Dq 1024
#define Fq 4096
#define Eq 8
#define NPAIR 16

// GEMM tiling: CTA 128x128x64, 8 compute warps (32x64) + 1 TMA producer, occ 2
#define NST 3
#define A_BYTES 16384
#define B_BYTES 16384
#define STAGE_BYTES (A_BYTES + B_BYTES)   // 32768
#define SMEM_REQ (2048 + NST*STAGE_BYTES)
#define NTHR 288

// tile counts
#define NT1 (32*16*NPAIR)    // 8192: nx(32) fastest, my(16), pair(16)

// prep kernel block ranges
#define XBLK 256
#define WBLK 8192

// ---------------- device scratch ----------------
__device__ __half g_xh [(size_t)Bq*Tq*Dq];        // x fp16        [B][T][D]
__device__ __half g_w1h[(size_t)Eq*Dq*Fq];        // W1 fp16       [E][D][F]
__device__ __half g_w2h[(size_t)Eq*Fq*Dq];        // W2 fp16       [E][F][D]
__device__ __half g_h  [(size_t)NPAIR*Tq*Fq];     // w*gelu(..)    [P][T][F]
__device__ float  g_part[Bq*8*Dq];
__device__ int    g_re[NPAIR];
__device__ float  g_rw[NPAIR];

// ---------------- helpers ----------------
__device__ __forceinline__ uint32_t cvt_smem(const void* p) {
    return (uint32_t)__cvta_generic_to_shared(p);
}
__device__ __forceinline__ void mbar_init(uint32_t a, uint32_t cnt) {
    asm volatile("mbarrier.init.shared.b64 [%0], %1;" :: "r"(a), "r"(cnt) : "memory");
}
__device__ __forceinline__ void mbar_expect(uint32_t a, uint32_t bytes) {
    asm volatile("mbarrier.arrive.expect_tx.shared.b64 _, [%0], %1;"
        :: "r"(a), "r"(bytes) : "memory");
}
__device__ __forceinline__ void mbar_arrive(uint32_t a) {
    asm volatile("mbarrier.arrive.shared.b64 _, [%0];" :: "r"(a) : "memory");
}
__device__ __forceinline__ void mbar_wait(uint32_t a, uint32_t parity) {
    asm volatile("{\n\t.reg .pred P;\n"
        "W%=:\n\t"
        "mbarrier.try_wait.parity.acquire.cta.shared::cta.b64 P, [%0], %1;\n\t"
        "@!P bra W%=;\n\t}"
        :: "r"(a), "r"(parity) : "memory");
}
__device__ __forceinline__ void mbar_wait_relaxed(uint32_t a, uint32_t parity) {
    asm volatile("{\n\t.reg .pred P;\n"
        "W%=:\n\t"
        "mbarrier.try_wait.parity.relaxed.cta.shared::cta.b64 P, [%0], %1;\n\t"
        "@!P bra W%=;\n\t}"
        :: "r"(a), "r"(parity) : "memory");
}
__device__ __forceinline__ void tma3(uint32_t dst, const CUtensorMap* m,
                                     int x, int y, int z, uint32_t mbar) {
    asm volatile(
        "cp.async.bulk.tensor.3d.shared::cta.global.tile.mbarrier::complete_tx::bytes "
        "[%0], [%1, {%2, %3, %4}], [%5];"
        :: "r"(dst), "l"(m), "r"(x), "r"(y), "r"(z), "r"(mbar) : "memory");
}
__device__ __forceinline__ uint32_t pkh2(float a, float b) {
    __half2 h = __floats2half2_rn(a, b);
    uint32_t r; memcpy(&r, &h, 4); return r;
}

// ---------------- merged prep: x conv+pool partials, W1 f2h, W2 f2h ----------------
__device__ __forceinline__ void f2h_body(const float4* __restrict__ s,
                                         uint4* __restrict__ d, size_t i) {
    const float4* sp = s + 4*i;
    float4 v0 = sp[0], v1 = sp[1], v2 = sp[2], v3 = sp[3];
    uint4 o0, o1;
    o0.x = pkh2(v0.x, v0.y); o0.y = pkh2(v0.z, v0.w);
    o0.z = pkh2(v1.x, v1.y); o0.w = pkh2(v1.z, v1.w);
    o1.x = pkh2(v2.x, v2.y); o1.y = pkh2(v2.z, v2.w);
    o1.z = pkh2(v3.x, v3.y); o1.w = pkh2(v3.z, v3.w);
    uint4* dp = d + 2*i;
    dp[0] = o0; dp[1] = o1;
}

__global__ void prep_kernel(const float* __restrict__ x,
                            const float* __restrict__ W1,
                            const float* __restrict__ W2,
                            __half* __restrict__ xh,
                            __half* __restrict__ w1h,
                            __half* __restrict__ w2h) {
    int j = blockIdx.x;
    if (j < XBLK) {
        int d  = (j & 3) * 256 + threadIdx.x;
        int tc = (j >> 2) & 7;
        int b  = j >> 5;
        const float* p = x  + ((size_t)b * Tq + (size_t)tc * 256) * Dq + d;
        __half*      q = xh + ((size_t)b * Tq + (size_t)tc * 256) * Dq + d;
        float s = 0.f;
        #pragma unroll 8
        for (int t = 0; t < 256; t++) {
            float v = p[(size_t)t * Dq];
            s += v;
            q[(size_t)t * Dq] = __float2half_rn(v);
        }
        g_part[(b*8 + tc)*Dq + d] = s;
    } else if (j < XBLK + WBLK) {
        size_t i = (size_t)(j - XBLK) * 256 + threadIdx.x;
        f2h_body((const float4*)W1, (uint4*)w1h, i);
    } else {
        size_t i = (size_t)(j - XBLK - WBLK) * 256 + threadIdx.x;
        f2h_body((const float4*)W2, (uint4*)w2h, i);
    }
}

// ---------------- router: 8 blocks, one per sample ----------------
__global__ void router8_kernel(const float* __restrict__ Wr) {
    __shared__ float pooled[Dq];
    __shared__ float logit[Eq];
    int b = blockIdx.x, tid = threadIdx.x;
    for (int d = tid; d < Dq; d += 256) {
        float s = 0.f;
        #pragma unroll
        for (int c = 0; c < 8; c++) s += g_part[(b*8 + c)*Dq + d];
        pooled[d] = s * (1.0f / (float)Tq);
    }
    __syncthreads();
    int warp = tid >> 5, lane = tid & 31;
    float s = 0.f;
    for (int d = lane; d < Dq; d += 32)
        s += pooled[d] * Wr[d*Eq + warp];
    #pragma unroll
    for (int o = 16; o > 0; o >>= 1) s += __shfl_xor_sync(0xffffffffu, s, o);
    if (lane == 0) logit[warp] = s;
    __syncthreads();
    if (tid == 0) {
        float best = -1e30f; int bi = 0;
        for (int e = 0; e < Eq; e++) { float v = logit[e]; if (v > best) { best = v; bi = e; } }
        float best2 = -1e30f; int bi2 = 0;
        for (int e = 0; e < Eq; e++) { if (e == bi) continue; float v = logit[e]; if (v > best2) { best2 = v; bi2 = e; } }
        float e1 = expf(best2 - best);
        float inv = 1.0f / (1.0f + e1);
        g_re[b*2+0] = bi;  g_rw[b*2+0] = inv;
        g_re[b*2+1] = bi2; g_rw[b*2+1] = e1 * inv;
    }
}

// ---------------- compute: warp tile 32x64, ldmatrix + mma ----------------
__device__ __forceinline__ void compute_iter(uint32_t sA, uint32_t sB,
        float acc[2][8][4], int wm, int wn, int lane) {
    #pragma unroll
    for (int ki = 0; ki < 4; ki++) {
        uint32_t a[2][4];
        #pragma unroll
        for (int mi = 0; mi < 2; mi++) {
            int r = wm*32 + mi*16 + (lane & 15);
            int c = ki*2 + (lane >> 4);
            uint32_t addr = sA + r*128 + ((c ^ (r & 7)) << 4);
            asm volatile("ldmatrix.sync.aligned.m8n8.x4.shared.b16 {%0,%1,%2,%3}, [%4];\n"
                : "=r"(a[mi][0]), "=r"(a[mi][1]), "=r"(a[mi][2]), "=r"(a[mi][3]) : "r"(addr));
        }
        uint32_t bf[8][2];
        #pragma unroll
        for (int n2 = 0; n2 < 4; n2++) {
            int kk = ki*16 + (lane & 15);
            int cl = n2*2 + (lane >> 4);
            uint32_t addr = sB + wn*8192 + kk*128 + (((cl ^ kk) & 7) << 4);
            asm volatile("ldmatrix.sync.aligned.m8n8.x4.trans.shared.b16 {%0,%1,%2,%3}, [%4];\n"
                : "=r"(bf[2*n2][0]), "=r"(bf[2*n2][1]), "=r"(bf[2*n2+1][0]), "=r"(bf[2*n2+1][1])
                : "r"(addr));
        }
        #pragma unroll
        for (int mi = 0; mi < 2; mi++)
            #pragma unroll
            for (int ni = 0; ni < 8; ni++) {
                asm volatile(
                    "mma.sync.aligned.m16n8k16.row.col.f32.f16.f16.f32 "
                    "{%0,%1,%2,%3}, {%4,%5,%6,%7}, {%8,%9}, {%0,%1,%2,%3};\n"
                    : "+f"(acc[mi][ni][0]), "+f"(acc[mi][ni][1]),
                      "+f"(acc[mi][ni][2]), "+f"(acc[mi][ni][3])
                    : "r"(a[mi][0]), "r"(a[mi][1]), "r"(a[mi][2]), "r"(a[mi][3]),
                      "r"(bf[ni][0]), "r"(bf[ni][1]));
            }
    }
}

// Rolling pipeline state (persistent gemm1).
struct PipeCur { int s; int ph; };
__device__ __forceinline__ void pipe_adv(PipeCur& c) {
    if (++c.s == NST) { c.s = 0; c.ph ^= 1; }
}

// ---------------- GEMM1 (persistent, measured-best): H = w*gelu(x@W1+b1) ----------------
__global__ void __launch_bounds__(NTHR, 2) gemm1_k(
        const __grid_constant__ CUtensorMap mA, const __grid_constant__ CUtensorMap mB,
        const float* __restrict__ b1) {
    extern __shared__ __align__(16) char smraw[];
    uint32_t u = cvt_smem(smraw);
    uint32_t base = (u + 1023) & ~1023u;
    uint32_t full = base, empty = base + 24;
    uint32_t st = base + 1024;
    int tid = threadIdx.x, lane = tid & 31, wid = tid >> 5;
    int wm = wid & 3, wn = wid >> 2;

    if (tid == 0) {
        #pragma unroll
        for (int s = 0; s < NST; s++) { mbar_init(full + s*8, 1); mbar_init(empty + s*8, 8); }
    }
    __syncthreads();

    if (wid == 8) {
        if (lane == 0) {
            PipeCur c = {0, 0};
            int it = 0;
            for (int t = blockIdx.x; t < NT1; t += gridDim.x) {
                int nx = t & 31, my = (t >> 5) & 15, pair = t >> 9;
                int e = g_re[pair], b = pair >> 1;
                int am0 = my*128, bn0 = nx*128;
                #pragma unroll 1
                for (int kt = 0; kt < 16; kt++, it++) {
                    if (it >= NST) mbar_wait_relaxed(empty + c.s*8, c.ph ^ 1);
                    uint32_t so = st + (uint32_t)c.s * STAGE_BYTES;
                    uint32_t mb = full + c.s*8;
                    mbar_expect(mb, STAGE_BYTES);
                    tma3(so,                &mA, kt*64,    am0,   b, mb);
                    tma3(so + A_BYTES,      &mB, bn0,      kt*64, e, mb);
                    tma3(so + A_BYTES+8192, &mB, bn0 + 64, kt*64, e, mb);
                    pipe_adv(c);
                }
            }
        }
    } else {
        PipeCur c = {0, 0};
        int tg = lane >> 2, tl = lane & 3;
        for (int t = blockIdx.x; t < NT1; t += gridDim.x) {
            int nx = t & 31, my = (t >> 5) & 15, pair = t >> 9;
            int e = g_re[pair];
            float w = g_rw[pair];
            float acc[2][8][4];
            #pragma unroll
            for (int i = 0; i < 2; i++) for (int j = 0; j < 8; j++)
                for (int q = 0; q < 4; q++) acc[i][j][q] = 0.f;
            #pragma unroll 1
            for (int kt = 0; kt < 16; kt++) {
                mbar_wait(full + c.s*8, c.ph);
                compute_iter(st + (uint32_t)c.s*STAGE_BYTES,
                             st + (uint32_t)c.s*STAGE_BYTES + A_BYTES, acc, wm, wn, lane);
                if (lane == 0) mbar_arrive(empty + c.s*8);
                pipe_adv(c);
            }
            const float* b1e = b1 + e*Fq + nx*128;
            __half* H = g_h + ((size_t)pair * Tq + (size_t)my*128) * Fq + nx*128;
            #pragma unroll
            for (int mi = 0; mi < 2; mi++) {
                #pragma unroll
                for (int ni = 0; ni < 8; ni++) {
                    int col  = wn*64 + ni*8 + tl*2;
                    int row0 = wm*32 + mi*16 + tg;
                    float bias0 = b1e[col], bias1 = b1e[col+1];
                    #pragma unroll
                    for (int rr = 0; rr < 2; rr++) {
                        float v0 = acc[mi][ni][rr*2+0] + bias0;
                        float v1 = acc[mi][ni][rr*2+1] + bias1;
                        v0 = 0.5f * v0 * (1.0f + erff(v0 * 0.7071067811865476f));
                        v1 = 0.5f * v1 * (1.0f + erff(v1 * 0.7071067811865476f));
                        *(__half2*)(H + (size_t)(row0 + rr*8) * Fq + col) =
                            __floats2half2_rn(v0*w, v1*w);
                    }
                }
            }
        }
    }
}

// ---------------- GEMM2 (per-tile grid, measured-best): out = sum_k H@W2 + bias ----------------
__device__ __forceinline__ void run_gemm(
        const CUtensorMap* mA, const CUtensorMap* mB,
        int am0, int bn0, int az0, int az1, int bz0, int bz1,
        int kseg, int nseg, float acc[2][8][4], char* smraw, int tid) {
    uint32_t u = cvt_smem(smraw);
    uint32_t base = (u + 1023) & ~1023u;
    uint32_t full = base, empty = base + 24;
    uint32_t st = base + 1024;
    int lane = tid & 31, wid = tid >> 5;
    int wm = wid & 3, wn = wid >> 2;
    int total = kseg * nseg;

    if (tid == 0) {
        #pragma unroll
        for (int s = 0; s < NST; s++) { mbar_init(full + s*8, 1); mbar_init(empty + s*8, 8); }
    }
    __syncthreads();

    if (wid == 8) {
        if (lane == 0) {
            #pragma unroll 1
            for (int kt = 0; kt < total; kt++) {
                int s = kt % NST;
                if (kt >= NST)
                    mbar_wait_relaxed(empty + s*8, (uint32_t)(((kt / NST) - 1) & 1));
                int seg = kt / kseg, kk = kt % kseg;
                int az = seg ? az1 : az0;
                int bz = seg ? bz1 : bz0;
                uint32_t so = st + (uint32_t)s * STAGE_BYTES;
                uint32_t mb = full + s*8;
                mbar_expect(mb, STAGE_BYTES);
                tma3(so,                mA, kk*64,    am0,   az, mb);
                tma3(so + A_BYTES,      mB, bn0,      kk*64, bz, mb);
                tma3(so + A_BYTES+8192, mB, bn0 + 64, kk*64, bz, mb);
            }
        }
    } else {
        #pragma unroll 1
        for (int kt = 0; kt < total; kt++) {
            int s = kt % NST;
            mbar_wait(full + s*8, (uint32_t)((kt / NST) & 1));
            compute_iter(st + (uint32_t)s*STAGE_BYTES, st + (uint32_t)s*STAGE_BYTES + A_BYTES,
                         acc, wm, wn, lane);
            if (lane == 0) mbar_arrive(empty + s*8);
        }
    }
}

__global__ void __launch_bounds__(NTHR, 2) gemm2_k(
        const __grid_constant__ CUtensorMap mA, const __grid_constant__ CUtensorMap mB,
        const float* __restrict__ b2, float* __restrict__ out) {
    extern __shared__ __align__(16) char smraw[];
    int b = blockIdx.z;
    int tid = threadIdx.x, lane = tid & 31, wid = tid >> 5;
    int wm = wid & 3, wn = wid >> 2;
    int e0 = g_re[b*2], e1 = g_re[b*2+1];

    float acc[2][8][4];
    #pragma unroll
    for (int i = 0; i < 2; i++) for (int j = 0; j < 8; j++)
        for (int q = 0; q < 4; q++) acc[i][j][q] = 0.f;

    run_gemm(&mA, &mB, blockIdx.y*128, blockIdx.x*128, b*2, b*2+1, e0, e1, 64, 2,
             acc, smraw, tid);
    if (wid >= 8) return;

    float w0 = g_rw[b*2], w1 = g_rw[b*2+1];
    const float* b2a = b2 + e0*Dq + blockIdx.x*128;
    const float* b2b = b2 + e1*Dq + blockIdx.x*128;
    float* O = out + ((size_t)b * Tq + (size_t)blockIdx.y*128) * Dq + blockIdx.x*128;
    int tg = lane >> 2, tl = lane & 3;
    #pragma unroll
    for (int mi = 0; mi < 2; mi++) {
        #pragma unroll
        for (int ni = 0; ni < 8; ni++) {
            int col  = wn*64 + ni*8 + tl*2;
            int row0 = wm*32 + mi*16 + tg;
            float bias0 = w0*b2a[col]   + w1*b2b[col];
            float bias1 = w0*b2a[col+1] + w1*b2b[col+1];
            #pragma unroll
            for (int rr = 0; rr < 2; rr++) {
                float2 v;
                v.x = acc[mi][ni][rr*2+0] + bias0;
                v.y = acc[mi][ni][rr*2+1] + bias1;
                *(float2*)(O + (size_t)(row0 + rr*8) * Dq + col) = v;
            }
        }
    }
}

// ---------------- host ----------------
typedef CUresult (*PFN_encode)(CUtensorMap*, CUtensorMapDataType, cuuint32_t, void*,
    const cuuint64_t*, const cuuint64_t*, const cuuint32_t*, const cuuint32_t*,
    CUtensorMapInterleave, CUtensorMapSwizzle, CUtensorMapL2promotion,
    CUtensorMapFloatOOBfill);

static void make_map(PFN_encode enc, CUtensorMap* m, void* ptr,
                     uint64_t d0, uint64_t d1, uint64_t d2, uint32_t boxy) {
    cuuint64_t dims[3]    = {d0, d1, d2};
    cuuint64_t strides[2] = {d0 * 2, d0 * d1 * 2};
    cuuint32_t box[3]     = {64, boxy, 1};
    cuuint32_t estr[3]    = {1, 1, 1};
    enc(m, CU_TENSOR_MAP_DATA_TYPE_FLOAT16, 3, ptr, dims, strides, box, estr,
        CU_TENSOR_MAP_INTERLEAVE_NONE, CU_TENSOR_MAP_SWIZZLE_128B,
        CU_TENSOR_MAP_L2_PROMOTION_L2_128B, CU_TENSOR_MAP_FLOAT_OOB_FILL_NONE);
}

extern "C" void kernel_launch(void* const* d_in, const int* in_sizes, int n_in,
                              void* d_out, int out_size) {
    const float* x  = (const float*)d_in[0];
    const float* Wr = (const float*)d_in[1];
    const float* W1 = (const float*)d_in[2];
    const float* b1 = (const float*)d_in[3];
    const float* W2 = (const float*)d_in[4];
    const float* b2 = (const float*)d_in[5];
    float* out = (float*)d_out;

    cudaFuncSetAttribute(gemm1_k, cudaFuncAttributeMaxDynamicSharedMemorySize, SMEM_REQ);
    cudaFuncSetAttribute(gemm2_k, cudaFuncAttributeMaxDynamicSharedMemorySize, SMEM_REQ);

    int smc = 148;
    cudaDeviceGetAttribute(&smc, cudaDevAttrMultiProcessorCount, 0);
    int npers = 2 * smc;
    int g1 = npers < NT1 ? npers : NT1;

    void *pxh, *pw1h, *pw2h, *ph;
    cudaGetSymbolAddress(&pxh,  g_xh);
    cudaGetSymbolAddress(&pw1h, g_w1h);
    cudaGetSymbolAddress(&pw2h, g_w2h);
    cudaGetSymbolAddress(&ph,   g_h);

    PFN_encode enc = nullptr;
#if CUDART_VERSION >= 12050
    cudaDriverEntryPointQueryResult qr;
    cudaGetDriverEntryPointByVersion("cuTensorMapEncodeTiled", (void**)&enc, 12000,
                                     cudaEnableDefault, &qr);
#else
    cudaDriverEntryPointQueryResult qr;
    cudaGetDriverEntryPoint("cuTensorMapEncodeTiled", (void**)&enc, cudaEnableDefault, &qr);
#endif

    CUtensorMap mX, mW1, mH, mW2;
    make_map(enc, &mX,  pxh,  Dq, Tq, Bq,    128);  // x   [B][T][D]
    make_map(enc, &mW1, pw1h, Fq, Dq, Eq,     64);  // W1  [E][D][F]
    make_map(enc, &mH,  ph,   Fq, Tq, NPAIR, 128);  // H   [P][T][F]
    make_map(enc, &mW2, pw2h, Dq, Fq, Eq,     64);  // W2  [E][F][D]

    // single stream (graph-safe, no stream/event allocations)
    prep_kernel<<<XBLK + 2*WBLK, 256>>>(x, W1, W2,
        (__half*)pxh, (__half*)pw1h, (__half*)pw2h);                               // 0
    router8_kernel<<<Bq, 256>>>(Wr);                                               // 1
    gemm1_k<<<g1, NTHR, SMEM_REQ>>>(mX, mW1, b1);                                  // 2 (persistent)
    gemm2_k<<<dim3(Dq/128, Tq/128, Bq), NTHR, SMEM_REQ>>>(mH, mW2, b2, out);       // 3 (per-tile)
}

// round 15
// speedup vs baseline: 1.0858x; 1.0601x over previous
#include <cuda_runtime.h>
#include <cuda.h>
#include <cuda_fp16.h>
#include <math.h>
#include <stdint.h>
#include <string.h>

// Problem dims
#define Bq 8
#define Tq 2048
#define Dq 1024
#define Fq 4096
#define Eq 8
#define NPAIR 16

// GEMM tiling: CTA 128x128x64, 8 compute warps (32x64) + 1 TMA producer, occ 2
#define NST 3
#define A_BYTES 16384
#define B_BYTES 16384
#define STAGE_BYTES (A_BYTES + B_BYTES)   // 32768
#define SMEM_REQ (2048 + NST*STAGE_BYTES)
#define NTHR 288

// tile counts
#define NT2 (8*16*Bq)        // 1024: nx(8) fastest, my(16), b(8)

// prep kernel block ranges
#define XBLK 256
#define WBLK 8192

// ---------------- device scratch ----------------
__device__ __half g_xh [(size_t)Bq*Tq*Dq];        // x fp16        [B][T][D]
__device__ __half g_w1h[(size_t)Eq*Dq*Fq];        // W1 fp16       [E][D][F]
__device__ __half g_w2h[(size_t)Eq*Fq*Dq];        // W2 fp16       [E][F][D]
__device__ __half g_h  [(size_t)NPAIR*Tq*Fq];     // w*gelu(..)    [P][T][F]
__device__ float  g_part[Bq*8*Dq];
__device__ int    g_re[NPAIR];
__device__ float  g_rw[NPAIR];

// ---------------- helpers ----------------
__device__ __forceinline__ uint32_t cvt_smem(const void* p) {
    return (uint32_t)__cvta_generic_to_shared(p);
}
__device__ __forceinline__ void mbar_init(uint32_t a, uint32_t cnt) {
    asm volatile("mbarrier.init.shared.b64 [%0], %1;" :: "r"(a), "r"(cnt) : "memory");
}
__device__ __forceinline__ void mbar_expect(uint32_t a, uint32_t bytes) {
    asm volatile("mbarrier.arrive.expect_tx.shared.b64 _, [%0], %1;"
        :: "r"(a), "r"(bytes) : "memory");
}
__device__ __forceinline__ void mbar_arrive(uint32_t a) {
    asm volatile("mbarrier.arrive.shared.b64 _, [%0];" :: "r"(a) : "memory");
}
__device__ __forceinline__ void mbar_wait(uint32_t a, uint32_t parity) {
    asm volatile("{\n\t.reg .pred P;\n"
        "W%=:\n\t"
        "mbarrier.try_wait.parity.acquire.cta.shared::cta.b64 P, [%0], %1;\n\t"
        "@!P bra W%=;\n\t}"
        :: "r"(a), "r"(parity) : "memory");
}
__device__ __forceinline__ void mbar_wait_relaxed(uint32_t a, uint32_t parity) {
    asm volatile("{\n\t.reg .pred P;\n"
        "W%=:\n\t"
        "mbarrier.try_wait.parity.relaxed.cta.shared::cta.b64 P, [%0], %1;\n\t"
        "@!P bra W%=;\n\t}"
        :: "r"(a), "r"(parity) : "memory");
}
__device__ __forceinline__ void tma3(uint32_t dst, const CUtensorMap* m,
                                     int x, int y, int z, uint32_t mbar) {
    asm volatile(
        "cp.async.bulk.tensor.3d.shared::cta.global.tile.mbarrier::complete_tx::bytes "
        "[%0], [%1, {%2, %3, %4}], [%5];"
        :: "r"(dst), "l"(m), "r"(x), "r"(y), "r"(z), "r"(mbar) : "memory");
}
__device__ __forceinline__ uint32_t pkh2(float a, float b) {
    __half2 h = __floats2half2_rn(a, b);
    uint32_t r; memcpy(&r, &h, 4); return r;
}
// fast GELU: 0.5*v*(1+tanh(0.79788456*(v + 0.044715 v^3))) with HW tanh
__device__ __forceinline__ float gelu_fast(float v) {
    float u = 0.7978845608028654f * fmaf(0.044715f * v, v * v, v);
    float t;
    asm("tanh.approx.f32 %0, %1;" : "=f"(t) : "f"(u));
    return 0.5f * v * (1.0f + t);
}

// ---------------- merged prep: x conv+pool partials, W1 f2h, W2 f2h ----------------
__device__ __forceinline__ void f2h_body(const float4* __restrict__ s,
                                         uint4* __restrict__ d, size_t i) {
    const float4* sp = s + 4*i;
    float4 v0 = sp[0], v1 = sp[1], v2 = sp[2], v3 = sp[3];
    uint4 o0, o1;
    o0.x = pkh2(v0.x, v0.y); o0.y = pkh2(v0.z, v0.w);
    o0.z = pkh2(v1.x, v1.y); o0.w = pkh2(v1.z, v1.w);
    o1.x = pkh2(v2.x, v2.y); o1.y = pkh2(v2.z, v2.w);
    o1.z = pkh2(v3.x, v3.y); o1.w = pkh2(v3.z, v3.w);
    uint4* dp = d + 2*i;
    dp[0] = o0; dp[1] = o1;
}

__global__ void prep_kernel(const float* __restrict__ x,
                            const float* __restrict__ W1,
                            const float* __restrict__ W2,
                            __half* __restrict__ xh,
                            __half* __restrict__ w1h,
                            __half* __restrict__ w2h) {
    int j = blockIdx.x;
    if (j < XBLK) {
        int d  = (j & 3) * 256 + threadIdx.x;
        int tc = (j >> 2) & 7;
        int b  = j >> 5;
        const float* p = x  + ((size_t)b * Tq + (size_t)tc * 256) * Dq + d;
        __half*      q = xh + ((size_t)b * Tq + (size_t)tc * 256) * Dq + d;
        float s = 0.f;
        #pragma unroll 8
        for (int t = 0; t < 256; t++) {
            float v = p[(size_t)t * Dq];
            s += v;
            q[(size_t)t * Dq] = __float2half_rn(v);
        }
        g_part[(b*8 + tc)*Dq + d] = s;
    } else if (j < XBLK + WBLK) {
        size_t i = (size_t)(j - XBLK) * 256 + threadIdx.x;
        f2h_body((const float4*)W1, (uint4*)w1h, i);
    } else {
        size_t i = (size_t)(j - XBLK - WBLK) * 256 + threadIdx.x;
        f2h_body((const float4*)W2, (uint4*)w2h, i);
    }
}

// ---------------- router: 8 blocks, one per sample ----------------
__global__ void router8_kernel(const float* __restrict__ Wr) {
    __shared__ float pooled[Dq];
    __shared__ float logit[Eq];
    int b = blockIdx.x, tid = threadIdx.x;
    for (int d = tid; d < Dq; d += 256) {
        float s = 0.f;
        #pragma unroll
        for (int c = 0; c < 8; c++) s += g_part[(b*8 + c)*Dq + d];
        pooled[d] = s * (1.0f / (float)Tq);
    }
    __syncthreads();
    int warp = tid >> 5, lane = tid & 31;
    float s = 0.f;
    for (int d = lane; d < Dq; d += 32)
        s += pooled[d] * Wr[d*Eq + warp];
    #pragma unroll
    for (int o = 16; o > 0; o >>= 1) s += __shfl_xor_sync(0xffffffffu, s, o);
    if (lane == 0) logit[warp] = s;
    __syncthreads();
    if (tid == 0) {
        float best = -1e30f; int bi = 0;
        for (int e = 0; e < Eq; e++) { float v = logit[e]; if (v > best) { best = v; bi = e; } }
        float best2 = -1e30f; int bi2 = 0;
        for (int e = 0; e < Eq; e++) { if (e == bi) continue; float v = logit[e]; if (v > best2) { best2 = v; bi2 = e; } }
        float e1 = expf(best2 - best);
        float inv = 1.0f / (1.0f + e1);
        g_re[b*2+0] = bi;  g_rw[b*2+0] = inv;
        g_re[b*2+1] = bi2; g_rw[b*2+1] = e1 * inv;
    }
}

// ---------------- compute: warp tile 32x64, ldmatrix + mma ----------------
__device__ __forceinline__ void compute_iter(uint32_t sA, uint32_t sB,
        float acc[2][8][4], int wm, int wn, int lane) {
    #pragma unroll
    for (int ki = 0; ki < 4; ki++) {
        uint32_t a[2][4];
        #pragma unroll
        for (int mi = 0; mi < 2; mi++) {
            int r = wm*32 + mi*16 + (lane & 15);
            int c = ki*2 + (lane >> 4);
            uint32_t addr = sA + r*128 + ((c ^ (r & 7)) << 4);
            asm volatile("ldmatrix.sync.aligned.m8n8.x4.shared.b16 {%0,%1,%2,%3}, [%4];\n"
                : "=r"(a[mi][0]), "=r"(a[mi][1]), "=r"(a[mi][2]), "=r"(a[mi][3]) : "r"(addr));
        }
        uint32_t bf[8][2];
        #pragma unroll
        for (int n2 = 0; n2 < 4; n2++) {
            int kk = ki*16 + (lane & 15);
            int cl = n2*2 + (lane >> 4);
            uint32_t addr = sB + wn*8192 + kk*128 + (((cl ^ kk) & 7) << 4);
            asm volatile("ldmatrix.sync.aligned.m8n8.x4.trans.shared.b16 {%0,%1,%2,%3}, [%4];\n"
                : "=r"(bf[2*n2][0]), "=r"(bf[2*n2][1]), "=r"(bf[2*n2+1][0]), "=r"(bf[2*n2+1][1])
                : "r"(addr));
        }
        #pragma unroll
        for (int mi = 0; mi < 2; mi++)
            #pragma unroll
            for (int ni = 0; ni < 8; ni++) {
                asm volatile(
                    "mma.sync.aligned.m16n8k16.row.col.f32.f16.f16.f32 "
                    "{%0,%1,%2,%3}, {%4,%5,%6,%7}, {%8,%9}, {%0,%1,%2,%3};\n"
                    : "+f"(acc[mi][ni][0]), "+f"(acc[mi][ni][1]),
                      "+f"(acc[mi][ni][2]), "+f"(acc[mi][ni][3])
                    : "r"(a[mi][0]), "r"(a[mi][1]), "r"(a[mi][2]), "r"(a[mi][3]),
                      "r"(bf[ni][0]), "r"(bf[ni][1]));
            }
    }
}

// Rolling pipeline state (persistent gemm2).
struct PipeCur { int s; int ph; };
__device__ __forceinline__ void pipe_adv(PipeCur& c) {
    if (++c.s == NST) { c.s = 0; c.ph ^= 1; }
}

// ---------------- shared per-tile mainloop (per-tile-grid kernels) ----------------
__device__ __forceinline__ void run_gemm(
        const CUtensorMap* mA, const CUtensorMap* mB,
        int am0, int bn0, int az0, int az1, int bz0, int bz1,
        int kseg, int nseg, float acc[2][8][4], char* smraw, int tid) {
    uint32_t u = cvt_smem(smraw);
    uint32_t base = (u + 1023) & ~1023u;
    uint32_t full = base, empty = base + 24;
    uint32_t st = base + 1024;
    int lane = tid & 31, wid = tid >> 5;
    int wm = wid & 3, wn = wid >> 2;
    int total = kseg * nseg;

    if (tid == 0) {
        #pragma unroll
        for (int s = 0; s < NST; s++) { mbar_init(full + s*8, 1); mbar_init(empty + s*8, 8); }
    }
    __syncthreads();

    if (wid == 8) {
        if (lane == 0) {
            #pragma unroll 1
            for (int kt = 0; kt < total; kt++) {
                int s = kt % NST;
                if (kt >= NST)
                    mbar_wait_relaxed(empty + s*8, (uint32_t)(((kt / NST) - 1) & 1));
                int seg = kt / kseg, kk = kt % kseg;
                int az = seg ? az1 : az0;
                int bz = seg ? bz1 : bz0;
                uint32_t so = st + (uint32_t)s * STAGE_BYTES;
                uint32_t mb = full + s*8;
                mbar_expect(mb, STAGE_BYTES);
                tma3(so,                mA, kk*64,    am0,   az, mb);
                tma3(so + A_BYTES,      mB, bn0,      kk*64, bz, mb);
                tma3(so + A_BYTES+8192, mB, bn0 + 64, kk*64, bz, mb);
            }
        }
    } else {
        #pragma unroll 1
        for (int kt = 0; kt < total; kt++) {
            int s = kt % NST;
            mbar_wait(full + s*8, (uint32_t)((kt / NST) & 1));
            compute_iter(st + (uint32_t)s*STAGE_BYTES, st + (uint32_t)s*STAGE_BYTES + A_BYTES,
                         acc, wm, wn, lane);
            if (lane == 0) mbar_arrive(empty + s*8);
        }
    }
}

// ---------------- GEMM1 (per-tile grid, R12-best): H = w*gelu_fast(x@W1+b1) ----------------
__global__ void __launch_bounds__(NTHR, 2) gemm1_k(
        const __grid_constant__ CUtensorMap mA, const __grid_constant__ CUtensorMap mB,
        const float* __restrict__ b1) {
    extern __shared__ __align__(16) char smraw[];
    int pair = blockIdx.z;
    int e = g_re[pair];
    float w = g_rw[pair];
    int b = pair >> 1;
    int tid = threadIdx.x, lane = tid & 31, wid = tid >> 5;
    int wm = wid & 3, wn = wid >> 2;

    float acc[2][8][4];
    #pragma unroll
    for (int i = 0; i < 2; i++) for (int j = 0; j < 8; j++)
        for (int q = 0; q < 4; q++) acc[i][j][q] = 0.f;

    run_gemm(&mA, &mB, blockIdx.y*128, blockIdx.x*128, b, b, e, e, 16, 1,
             acc, smraw, tid);
    if (wid >= 8) return;

    const float* b1e = b1 + e*Fq + blockIdx.x*128;
    __half* H = g_h + ((size_t)pair * Tq + (size_t)blockIdx.y*128) * Fq + blockIdx.x*128;
    int tg = lane >> 2, tl = lane & 3;
    #pragma unroll
    for (int mi = 0; mi < 2; mi++) {
        #pragma unroll
        for (int ni = 0; ni < 8; ni++) {
            int col  = wn*64 + ni*8 + tl*2;
            int row0 = wm*32 + mi*16 + tg;
            float bias0 = b1e[col], bias1 = b1e[col+1];
            #pragma unroll
            for (int rr = 0; rr < 2; rr++) {
                float v0 = gelu_fast(acc[mi][ni][rr*2+0] + bias0);
                float v1 = gelu_fast(acc[mi][ni][rr*2+1] + bias1);
                *(__half2*)(H + (size_t)(row0 + rr*8) * Fq + col) = __floats2half2_rn(v0*w, v1*w);
            }
        }
    }
}

// ---------------- GEMM2 (persistent, hoisted decode): out = sum_k H@W2 + bias ----------------
__global__ void __launch_bounds__(NTHR, 2) gemm2_k(
        const __grid_constant__ CUtensorMap mA, const __grid_constant__ CUtensorMap mB,
        const float* __restrict__ b2, float* __restrict__ out) {
    extern __shared__ __align__(16) char smraw[];
    uint32_t u = cvt_smem(smraw);
    uint32_t base = (u + 1023) & ~1023u;
    uint32_t full = base, empty = base + 24;
    uint32_t st = base + 1024;
    int tid = threadIdx.x, lane = tid & 31, wid = tid >> 5;
    int wm = wid & 3, wn = wid >> 2;

    if (tid == 0) {
        #pragma unroll
        for (int s = 0; s < NST; s++) { mbar_init(full + s*8, 1); mbar_init(empty + s*8, 8); }
    }
    __syncthreads();

    if (wid == 8) {
        if (lane == 0) {
            PipeCur c = {0, 0};
            int it = 0;
            for (int t = blockIdx.x; t < NT2; t += gridDim.x) {
                int nx = t & 7, my = (t >> 3) & 15, b = t >> 7;
                int am0 = my*128, bn0 = nx*128;
                int e0 = g_re[b*2], e1 = g_re[b*2+1];    // hoisted: one load pair per tile
                #pragma unroll 1
                for (int seg = 0; seg < 2; seg++) {
                    int az = b*2 + seg;
                    int bz = seg ? e1 : e0;
                    #pragma unroll 1
                    for (int kk = 0; kk < 64; kk++, it++) {
                        if (it >= NST) mbar_wait_relaxed(empty + c.s*8, c.ph ^ 1);
                        uint32_t so = st + (uint32_t)c.s * STAGE_BYTES;
                        uint32_t mb = full + c.s*8;
                        mbar_expect(mb, STAGE_BYTES);
                        tma3(so,                &mA, kk*64,    am0,   az, mb);
                        tma3(so + A_BYTES,      &mB, bn0,      kk*64, bz, mb);
                        tma3(so + A_BYTES+8192, &mB, bn0 + 64, kk*64, bz, mb);
                        pipe_adv(c);
                    }
                }
            }
        }
    } else {
        PipeCur c = {0, 0};
        int tg = lane >> 2, tl = lane & 3;
        for (int t = blockIdx.x; t < NT2; t += gridDim.x) {
            int nx = t & 7, my = (t >> 3) & 15, b = t >> 7;
            float acc[2][8][4];
            #pragma unroll
            for (int i = 0; i < 2; i++) for (int j = 0; j < 8; j++)
                for (int q = 0; q < 4; q++) acc[i][j][q] = 0.f;
            #pragma unroll 1
            for (int kt = 0; kt < 128; kt++) {
                mbar_wait(full + c.s*8, c.ph);
                compute_iter(st + (uint32_t)c.s*STAGE_BYTES,
                             st + (uint32_t)c.s*STAGE_BYTES + A_BYTES, acc, wm, wn, lane);
                if (lane == 0) mbar_arrive(empty + c.s*8);
                pipe_adv(c);
            }
            int e0 = g_re[b*2], e1 = g_re[b*2+1];
            float w0 = g_rw[b*2], w1 = g_rw[b*2+1];
            const float* b2a = b2 + e0*Dq + nx*128;
            const float* b2b = b2 + e1*Dq + nx*128;
            float* O = out + ((size_t)b * Tq + (size_t)my*128) * Dq + nx*128;
            #pragma unroll
            for (int mi = 0; mi < 2; mi++) {
                #pragma unroll
                for (int ni = 0; ni < 8; ni++) {
                    int col  = wn*64 + ni*8 + tl*2;
                    int row0 = wm*32 + mi*16 + tg;
                    float bias0 = w0*b2a[col]   + w1*b2b[col];
                    float bias1 = w0*b2a[col+1] + w1*b2b[col+1];
                    #pragma unroll
                    for (int rr = 0; rr < 2; rr++) {
                        float2 v;
                        v.x = acc[mi][ni][rr*2+0] + bias0;
                        v.y = acc[mi][ni][rr*2+1] + bias1;
                        *(float2*)(O + (size_t)(row0 + rr*8) * Dq + col) = v;
                    }
                }
            }
        }
    }
}

// ---------------- host ----------------
typedef CUresult (*PFN_encode)(CUtensorMap*, CUtensorMapDataType, cuuint32_t, void*,
    const cuuint64_t*, const cuuint64_t*, const cuuint32_t*, const cuuint32_t*,
    CUtensorMapInterleave, CUtensorMapSwizzle, CUtensorMapL2promotion,
    CUtensorMapFloatOOBfill);

static void make_map(PFN_encode enc, CUtensorMap* m, void* ptr,
                     uint64_t d0, uint64_t d1, uint64_t d2, uint32_t boxy) {
    cuuint64_t dims[3]    = {d0, d1, d2};
    cuuint64_t strides[2] = {d0 * 2, d0 * d1 * 2};
    cuuint32_t box[3]     = {64, boxy, 1};
    cuuint32_t estr[3]    = {1, 1, 1};
    enc(m, CU_TENSOR_MAP_DATA_TYPE_FLOAT16, 3, ptr, dims, strides, box, estr,
        CU_TENSOR_MAP_INTERLEAVE_NONE, CU_TENSOR_MAP_SWIZZLE_128B,
        CU_TENSOR_MAP_L2_PROMOTION_L2_128B, CU_TENSOR_MAP_FLOAT_OOB_FILL_NONE);
}

extern "C" void kernel_launch(void* const* d_in, const int* in_sizes, int n_in,
                              void* d_out, int out_size) {
    const float* x  = (const float*)d_in[0];
    const float* Wr = (const float*)d_in[1];
    const float* W1 = (const float*)d_in[2];
    const float* b1 = (const float*)d_in[3];
    const float* W2 = (const float*)d_in[4];
    const float* b2 = (const float*)d_in[5];
    float* out = (float*)d_out;

    cudaFuncSetAttribute(gemm1_k, cudaFuncAttributeMaxDynamicSharedMemorySize, SMEM_REQ);
    cudaFuncSetAttribute(gemm2_k, cudaFuncAttributeMaxDynamicSharedMemorySize, SMEM_REQ);

    int smc = 148;
    cudaDeviceGetAttribute(&smc, cudaDevAttrMultiProcessorCount, 0);
    int npers = 2 * smc;
    int g2 = npers < NT2 ? npers : NT2;

    void *pxh, *pw1h, *pw2h, *ph;
    cudaGetSymbolAddress(&pxh,  g_xh);
    cudaGetSymbolAddress(&pw1h, g_w1h);
    cudaGetSymbolAddress(&pw2h, g_w2h);
    cudaGetSymbolAddress(&ph,   g_h);

    PFN_encode enc = nullptr;
#if CUDART_VERSION >= 12050
    cudaDriverEntryPointQueryResult qr;
    cudaGetDriverEntryPointByVersion("cuTensorMapEncodeTiled", (void**)&enc, 12000,
                                     cudaEnableDefault, &qr);
#else
    cudaDriverEntryPointQueryResult qr;
    cudaGetDriverEntryPoint("cuTensorMapEncodeTiled", (void**)&enc, cudaEnableDefault, &qr);
#endif

    CUtensorMap mX, mW1, mH, mW2;
    make_map(enc, &mX,  pxh,  Dq, Tq, Bq,    128);  // x   [B][T][D]
    make_map(enc, &mW1, pw1h, Fq, Dq, Eq,     64);  // W1  [E][D][F]
    make_map(enc, &mH,  ph,   Fq, Tq, NPAIR, 128);  // H   [P][T][F]
    make_map(enc, &mW2, pw2h, Dq, Fq, Eq,     64);  // W2  [E][F][D]

    // single stream (graph-safe, no stream/event allocations)
    prep_kernel<<<XBLK + 2*WBLK, 256>>>(x, W1, W2,
        (__half*)pxh, (__half*)pw1h, (__half*)pw2h);                               // 0
    router8_kernel<<<Bq, 256>>>(Wr);                                               // 1
    gemm1_k<<<dim3(Fq/128, Tq/128, NPAIR), NTHR, SMEM_REQ>>>(mX, mW1, b1);         // 2 (per-tile)
    gemm2_k<<<g2, NTHR, SMEM_REQ>>>(mH, mW2, b2, out);                             // 3 (persistent)
}

// round 16
// speedup vs baseline: 1.1114x; 1.0236x over previous
#include <cuda_runtime.h>
#include <cuda.h>
#include <cuda_fp16.h>
#include <math.h>
#include <stdint.h>
#include <string.h>

// Problem dims
#define Bq 8
#define Tq 2048
#define Dq 1024
#define Fq 4096
#define Eq 8
#define NPAIR 16

// GEMM tiling: CTA 128x128x64, 8 compute warps (32x64) + 1 TMA producer, occ 2
#define NST 3
#define A_BYTES 16384
#define B_BYTES 16384
#define STAGE_BYTES (A_BYTES + B_BYTES)   // 32768
#define SMEM_REQ (2048 + NST*STAGE_BYTES)
#define NTHR 288

// prep kernel block ranges
#define XBLK 256
#define WBLK 8192

// ---------------- device scratch ----------------
__device__ __half g_xh [(size_t)Bq*Tq*Dq];        // x fp16        [B][T][D]
__device__ __half g_w1h[(size_t)Eq*Dq*Fq];        // W1 fp16       [E][D][F]
__device__ __half g_w2h[(size_t)Eq*Fq*Dq];        // W2 fp16       [E][F][D]
__device__ __half g_h  [(size_t)NPAIR*Tq*Fq];     // w*gelu(..)    [P][T][F]
__device__ float  g_part[Bq*8*Dq];
__device__ int    g_re[NPAIR];
__device__ float  g_rw[NPAIR];

// ---------------- helpers ----------------
__device__ __forceinline__ uint32_t cvt_smem(const void* p) {
    return (uint32_t)__cvta_generic_to_shared(p);
}
__device__ __forceinline__ void mbar_init(uint32_t a, uint32_t cnt) {
    asm volatile("mbarrier.init.shared.b64 [%0], %1;" :: "r"(a), "r"(cnt) : "memory");
}
__device__ __forceinline__ void mbar_expect(uint32_t a, uint32_t bytes) {
    asm volatile("mbarrier.arrive.expect_tx.shared.b64 _, [%0], %1;"
        :: "r"(a), "r"(bytes) : "memory");
}
__device__ __forceinline__ void mbar_arrive(uint32_t a) {
    asm volatile("mbarrier.arrive.shared.b64 _, [%0];" :: "r"(a) : "memory");
}
__device__ __forceinline__ void mbar_wait(uint32_t a, uint32_t parity) {
    asm volatile("{\n\t.reg .pred P;\n"
        "W%=:\n\t"
        "mbarrier.try_wait.parity.acquire.cta.shared::cta.b64 P, [%0], %1;\n\t"
        "@!P bra W%=;\n\t}"
        :: "r"(a), "r"(parity) : "memory");
}
__device__ __forceinline__ void mbar_wait_relaxed(uint32_t a, uint32_t parity) {
    asm volatile("{\n\t.reg .pred P;\n"
        "W%=:\n\t"
        "mbarrier.try_wait.parity.relaxed.cta.shared::cta.b64 P, [%0], %1;\n\t"
        "@!P bra W%=;\n\t}"
        :: "r"(a), "r"(parity) : "memory");
}
__device__ __forceinline__ void tma3(uint32_t dst, const CUtensorMap* m,
                                     int x, int y, int z, uint32_t mbar) {
    asm volatile(
        "cp.async.bulk.tensor.3d.shared::cta.global.tile.mbarrier::complete_tx::bytes "
        "[%0], [%1, {%2, %3, %4}], [%5];"
        :: "r"(dst), "l"(m), "r"(x), "r"(y), "r"(z), "r"(mbar) : "memory");
}
__device__ __forceinline__ uint32_t pkh2(float a, float b) {
    __half2 h = __floats2half2_rn(a, b);
    uint32_t r; memcpy(&r, &h, 4); return r;
}
// fast GELU: 0.5*v*(1+tanh(0.79788456*(v + 0.044715 v^3))) with HW tanh
__device__ __forceinline__ float gelu_fast(float v) {
    float u = 0.7978845608028654f * fmaf(0.044715f * v, v * v, v);
    float t;
    asm("tanh.approx.f32 %0, %1;" : "=f"(t) : "f"(u));
    return 0.5f * v * (1.0f + t);
}

// ---------------- merged prep: x conv+pool partials, W1 f2h, W2 f2h ----------------
__device__ __forceinline__ void f2h_body(const float4* __restrict__ s,
                                         uint4* __restrict__ d, size_t i) {
    const float4* sp = s + 4*i;
    float4 v0 = sp[0], v1 = sp[1], v2 = sp[2], v3 = sp[3];
    uint4 o0, o1;
    o0.x = pkh2(v0.x, v0.y); o0.y = pkh2(v0.z, v0.w);
    o0.z = pkh2(v1.x, v1.y); o0.w = pkh2(v1.z, v1.w);
    o1.x = pkh2(v2.x, v2.y); o1.y = pkh2(v2.z, v2.w);
    o1.z = pkh2(v3.x, v3.y); o1.w = pkh2(v3.z, v3.w);
    uint4* dp = d + 2*i;
    dp[0] = o0; dp[1] = o1;
}

__global__ void prep_kernel(const float* __restrict__ x,
                            const float* __restrict__ W1,
                            const float* __restrict__ W2,
                            __half* __restrict__ xh,
                            __half* __restrict__ w1h,
                            __half* __restrict__ w2h) {
    int j = blockIdx.x;
    if (j < XBLK) {
        int d  = (j & 3) * 256 + threadIdx.x;
        int tc = (j >> 2) & 7;
        int b  = j >> 5;
        const float* p = x  + ((size_t)b * Tq + (size_t)tc * 256) * Dq + d;
        __half*      q = xh + ((size_t)b * Tq + (size_t)tc * 256) * Dq + d;
        float s = 0.f;
        #pragma unroll 8
        for (int t = 0; t < 256; t++) {
            float v = p[(size_t)t * Dq];
            s += v;
            q[(size_t)t * Dq] = __float2half_rn(v);
        }
        g_part[(b*8 + tc)*Dq + d] = s;
    } else if (j < XBLK + WBLK) {
        size_t i = (size_t)(j - XBLK) * 256 + threadIdx.x;
        f2h_body((const float4*)W1, (uint4*)w1h, i);
    } else {
        size_t i = (size_t)(j - XBLK - WBLK) * 256 + threadIdx.x;
        f2h_body((const float4*)W2, (uint4*)w2h, i);
    }
}

// ---------------- router: 8 blocks, one per sample ----------------
__global__ void router8_kernel(const float* __restrict__ Wr) {
    __shared__ float pooled[Dq];
    __shared__ float logit[Eq];
    int b = blockIdx.x, tid = threadIdx.x;
    for (int d = tid; d < Dq; d += 256) {
        float s = 0.f;
        #pragma unroll
        for (int c = 0; c < 8; c++) s += g_part[(b*8 + c)*Dq + d];
        pooled[d] = s * (1.0f / (float)Tq);
    }
    __syncthreads();
    int warp = tid >> 5, lane = tid & 31;
    float s = 0.f;
    for (int d = lane; d < Dq; d += 32)
        s += pooled[d] * Wr[d*Eq + warp];
    #pragma unroll
    for (int o = 16; o > 0; o >>= 1) s += __shfl_xor_sync(0xffffffffu, s, o);
    if (lane == 0) logit[warp] = s;
    __syncthreads();
    if (tid == 0) {
        float best = -1e30f; int bi = 0;
        for (int e = 0; e < Eq; e++) { float v = logit[e]; if (v > best) { best = v; bi = e; } }
        float best2 = -1e30f; int bi2 = 0;
        for (int e = 0; e < Eq; e++) { if (e == bi) continue; float v = logit[e]; if (v > best2) { best2 = v; bi2 = e; } }
        float e1 = expf(best2 - best);
        float inv = 1.0f / (1.0f + e1);
        g_re[b*2+0] = bi;  g_rw[b*2+0] = inv;
        g_re[b*2+1] = bi2; g_rw[b*2+1] = e1 * inv;
    }
}

// ---------------- compute: warp tile 32x64, ldmatrix + mma ----------------
__device__ __forceinline__ void compute_iter(uint32_t sA, uint32_t sB,
        float acc[2][8][4], int wm, int wn, int lane) {
    #pragma unroll
    for (int ki = 0; ki < 4; ki++) {
        uint32_t a[2][4];
        #pragma unroll
        for (int mi = 0; mi < 2; mi++) {
            int r = wm*32 + mi*16 + (lane & 15);
            int c = ki*2 + (lane >> 4);
            uint32_t addr = sA + r*128 + ((c ^ (r & 7)) << 4);
            asm volatile("ldmatrix.sync.aligned.m8n8.x4.shared.b16 {%0,%1,%2,%3}, [%4];\n"
                : "=r"(a[mi][0]), "=r"(a[mi][1]), "=r"(a[mi][2]), "=r"(a[mi][3]) : "r"(addr));
        }
        uint32_t bf[8][2];
        #pragma unroll
        for (int n2 = 0; n2 < 4; n2++) {
            int kk = ki*16 + (lane & 15);
            int cl = n2*2 + (lane >> 4);
            uint32_t addr = sB + wn*8192 + kk*128 + (((cl ^ kk) & 7) << 4);
            asm volatile("ldmatrix.sync.aligned.m8n8.x4.trans.shared.b16 {%0,%1,%2,%3}, [%4];\n"
                : "=r"(bf[2*n2][0]), "=r"(bf[2*n2][1]), "=r"(bf[2*n2+1][0]), "=r"(bf[2*n2+1][1])
                : "r"(addr));
        }
        #pragma unroll
        for (int mi = 0; mi < 2; mi++)
            #pragma unroll
            for (int ni = 0; ni < 8; ni++) {
                asm volatile(
                    "mma.sync.aligned.m16n8k16.row.col.f32.f16.f16.f32 "
                    "{%0,%1,%2,%3}, {%4,%5,%6,%7}, {%8,%9}, {%0,%1,%2,%3};\n"
                    : "+f"(acc[mi][ni][0]), "+f"(acc[mi][ni][1]),
                      "+f"(acc[mi][ni][2]), "+f"(acc[mi][ni][3])
                    : "r"(a[mi][0]), "r"(a[mi][1]), "r"(a[mi][2]), "r"(a[mi][3]),
                      "r"(bf[ni][0]), "r"(bf[ni][1]));
            }
    }
}

// ---------------- shared per-tile mainloop ----------------
__device__ __forceinline__ void run_gemm(
        const CUtensorMap* mA, const CUtensorMap* mB,
        int am0, int bn0, int az0, int az1, int bz0, int bz1,
        int kseg, int nseg, float acc[2][8][4], char* smraw, int tid) {
    uint32_t u = cvt_smem(smraw);
    uint32_t base = (u + 1023) & ~1023u;
    uint32_t full = base, empty = base + 24;
    uint32_t st = base + 1024;
    int lane = tid & 31, wid = tid >> 5;
    int wm = wid & 3, wn = wid >> 2;
    int total = kseg * nseg;

    if (tid == 0) {
        #pragma unroll
        for (int s = 0; s < NST; s++) { mbar_init(full + s*8, 1); mbar_init(empty + s*8, 8); }
    }
    __syncthreads();

    if (wid == 8) {
        if (lane == 0) {
            #pragma unroll 1
            for (int kt = 0; kt < total; kt++) {
                int s = kt % NST;
                if (kt >= NST)
                    mbar_wait_relaxed(empty + s*8, (uint32_t)(((kt / NST) - 1) & 1));
                int seg = kt / kseg, kk = kt % kseg;
                int az = seg ? az1 : az0;
                int bz = seg ? bz1 : bz0;
                uint32_t so = st + (uint32_t)s * STAGE_BYTES;
                uint32_t mb = full + s*8;
                mbar_expect(mb, STAGE_BYTES);
                tma3(so,                mA, kk*64,    am0,   az, mb);
                tma3(so + A_BYTES,      mB, bn0,      kk*64, bz, mb);
                tma3(so + A_BYTES+8192, mB, bn0 + 64, kk*64, bz, mb);
            }
        }
    } else {
        #pragma unroll 1
        for (int kt = 0; kt < total; kt++) {
            int s = kt % NST;
            mbar_wait(full + s*8, (uint32_t)((kt / NST) & 1));
            compute_iter(st + (uint32_t)s*STAGE_BYTES, st + (uint32_t)s*STAGE_BYTES + A_BYTES,
                         acc, wm, wn, lane);
            if (lane == 0) mbar_arrive(empty + s*8);
        }
    }
}

// ---------------- GEMM1 (per-tile grid): H = w*gelu_fast(x@W1+b1) ----------------
__global__ void __launch_bounds__(NTHR, 2) gemm1_k(
        const __grid_constant__ CUtensorMap mA, const __grid_constant__ CUtensorMap mB,
        const float* __restrict__ b1) {
    extern __shared__ __align__(16) char smraw[];
    int pair = blockIdx.z;
    int e = g_re[pair];
    float w = g_rw[pair];
    int b = pair >> 1;
    int tid = threadIdx.x, lane = tid & 31, wid = tid >> 5;
    int wm = wid & 3, wn = wid >> 2;

    float acc[2][8][4];
    #pragma unroll
    for (int i = 0; i < 2; i++) for (int j = 0; j < 8; j++)
        for (int q = 0; q < 4; q++) acc[i][j][q] = 0.f;

    run_gemm(&mA, &mB, blockIdx.y*128, blockIdx.x*128, b, b, e, e, 16, 1,
             acc, smraw, tid);
    if (wid >= 8) return;

    const float* b1e = b1 + e*Fq + blockIdx.x*128;
    __half* H = g_h + ((size_t)pair * Tq + (size_t)blockIdx.y*128) * Fq + blockIdx.x*128;
    int tg = lane >> 2, tl = lane & 3;
    #pragma unroll
    for (int mi = 0; mi < 2; mi++) {
        #pragma unroll
        for (int ni = 0; ni < 8; ni++) {
            int col  = wn*64 + ni*8 + tl*2;
            int row0 = wm*32 + mi*16 + tg;
            float bias0 = b1e[col], bias1 = b1e[col+1];
            #pragma unroll
            for (int rr = 0; rr < 2; rr++) {
                float v0 = gelu_fast(acc[mi][ni][rr*2+0] + bias0);
                float v1 = gelu_fast(acc[mi][ni][rr*2+1] + bias1);
                *(__half2*)(H + (size_t)(row0 + rr*8) * Fq + col) = __floats2half2_rn(v0*w, v1*w);
            }
        }
    }
}

// ---------------- GEMM2 (per-tile grid): out = sum_k H@W2 + combined bias ----------------
__global__ void __launch_bounds__(NTHR, 2) gemm2_k(
        const __grid_constant__ CUtensorMap mA, const __grid_constant__ CUtensorMap mB,
        const float* __restrict__ b2, float* __restrict__ out) {
    extern __shared__ __align__(16) char smraw[];
    int b = blockIdx.z;
    int tid = threadIdx.x, lane = tid & 31, wid = tid >> 5;
    int wm = wid & 3, wn = wid >> 2;
    int e0 = g_re[b*2], e1 = g_re[b*2+1];

    float acc[2][8][4];
    #pragma unroll
    for (int i = 0; i < 2; i++) for (int j = 0; j < 8; j++)
        for (int q = 0; q < 4; q++) acc[i][j][q] = 0.f;

    run_gemm(&mA, &mB, blockIdx.y*128, blockIdx.x*128, b*2, b*2+1, e0, e1, 64, 2,
             acc, smraw, tid);
    if (wid >= 8) return;

    float w0 = g_rw[b*2], w1 = g_rw[b*2+1];
    const float* b2a = b2 + e0*Dq + blockIdx.x*128;
    const float* b2b = b2 + e1*Dq + blockIdx.x*128;
    float* O = out + ((size_t)b * Tq + (size_t)blockIdx.y*128) * Dq + blockIdx.x*128;
    int tg = lane >> 2, tl = lane & 3;
    #pragma unroll
    for (int mi = 0; mi < 2; mi++) {
        #pragma unroll
        for (int ni = 0; ni < 8; ni++) {
            int col  = wn*64 + ni*8 + tl*2;
            int row0 = wm*32 + mi*16 + tg;
            float bias0 = w0*b2a[col]   + w1*b2b[col];
            float bias1 = w0*b2a[col+1] + w1*b2b[col+1];
            #pragma unroll
            for (int rr = 0; rr < 2; rr++) {
                float2 v;
                v.x = acc[mi][ni][rr*2+0] + bias0;
                v.y = acc[mi][ni][rr*2+1] + bias1;
                *(float2*)(O + (size_t)(row0 + rr*8) * Dq + col) = v;
            }
        }
    }
}

// ---------------- host ----------------
typedef CUresult (*PFN_encode)(CUtensorMap*, CUtensorMapDataType, cuuint32_t, void*,
    const cuuint64_t*, const cuuint64_t*, const cuuint32_t*, const cuuint32_t*,
    CUtensorMapInterleave, CUtensorMapSwizzle, CUtensorMapL2promotion,
    CUtensorMapFloatOOBfill);

static void make_map(PFN_encode enc, CUtensorMap* m, void* ptr,
                     uint64_t d0, uint64_t d1, uint64_t d2, uint32_t boxy) {
    cuuint64_t dims[3]    = {d0, d1, d2};
    cuuint64_t strides[2] = {d0 * 2, d0 * d1 * 2};
    cuuint32_t box[3]     = {64, boxy, 1};
    cuuint32_t estr[3]    = {1, 1, 1};
    enc(m, CU_TENSOR_MAP_DATA_TYPE_FLOAT16, 3, ptr, dims, strides, box, estr,
        CU_TENSOR_MAP_INTERLEAVE_NONE, CU_TENSOR_MAP_SWIZZLE_128B,
        CU_TENSOR_MAP_L2_PROMOTION_L2_128B, CU_TENSOR_MAP_FLOAT_OOB_FILL_NONE);
}

extern "C" void kernel_launch(void* const* d_in, const int* in_sizes, int n_in,
                              void* d_out, int out_size) {
    const float* x  = (const float*)d_in[0];
    const float* Wr = (const float*)d_in[1];
    const float* W1 = (const float*)d_in[2];
    const float* b1 = (const float*)d_in[3];
    const float* W2 = (const float*)d_in[4];
    const float* b2 = (const float*)d_in[5];
    float* out = (float*)d_out;

    cudaFuncSetAttribute(gemm1_k, cudaFuncAttributeMaxDynamicSharedMemorySize, SMEM_REQ);
    cudaFuncSetAttribute(gemm2_k, cudaFuncAttributeMaxDynamicSharedMemorySize, SMEM_REQ);

    void *pxh, *pw1h, *pw2h, *ph;
    cudaGetSymbolAddress(&pxh,  g_xh);
    cudaGetSymbolAddress(&pw1h, g_w1h);
    cudaGetSymbolAddress(&pw2h, g_w2h);
    cudaGetSymbolAddress(&ph,   g_h);

    PFN_encode enc = nullptr;
#if CUDART_VERSION >= 12050
    cudaDriverEntryPointQueryResult qr;
    cudaGetDriverEntryPointByVersion("cuTensorMapEncodeTiled", (void**)&enc, 12000,
                                     cudaEnableDefault, &qr);
#else
    cudaDriverEntryPointQueryResult qr;
    cudaGetDriverEntryPoint("cuTensorMapEncodeTiled", (void**)&enc, cudaEnableDefault, &qr);
#endif

    CUtensorMap mX, mW1, mH, mW2;
    make_map(enc, &mX,  pxh,  Dq, Tq, Bq,    128);  // x   [B][T][D]
    make_map(enc, &mW1, pw1h, Fq, Dq, Eq,     64);  // W1  [E][D][F]
    make_map(enc, &mH,  ph,   Fq, Tq, NPAIR, 128);  // H   [P][T][F]
    make_map(enc, &mW2, pw2h, Dq, Fq, Eq,     64);  // W2  [E][F][D]

    // single stream (graph-safe, no stream/event allocations)
    prep_kernel<<<XBLK + 2*WBLK, 256>>>(x, W1, W2,
        (__half*)pxh, (__half*)pw1h, (__half*)pw2h);                               // 0
    router8_kernel<<<Bq, 256>>>(Wr);                                               // 1
    gemm1_k<<<dim3(Fq/128, Tq/128, NPAIR), NTHR, SMEM_REQ>>>(mX, mW1, b1);         // 2
    gemm2_k<<<dim3(Dq/128, Tq/128, Bq), NTHR, SMEM_REQ>>>(mH, mW2, b2, out);       // 3
}